// round 5
// baseline (speedup 1.0000x reference)
#include <cuda_runtime.h>
#include <math_constants.h>

// VectorQuantizer: B=32, D=64, H=W=32, K=1024
// Output layout (f32 concat): [loss(1)][quantized BxDxHxW (2097152)][indices BxHW (32768)]

#define NB 32
#define ND 64
#define NHW 1024
#define NK 1024
#define NPTS 32768            // B*H*W
#define MAIN_BLOCKS 128       // each block handles 256 points (2 per thread)
#define MAIN_THREADS 128
#define CODES_PER_ITER 8
#define NITER (NK / CODES_PER_ITER)   // 128

__device__ float  g_e2[NK];
__device__ double g_partials[MAIN_BLOCKS];

// ---------------------------------------------------------------------------
// Packed f32x2 helpers (Blackwell sm_103a; ptxas never auto-fuses these)
// ---------------------------------------------------------------------------
__device__ __forceinline__ unsigned long long pack2(float a, float b) {
    unsigned long long r;
    asm("mov.b64 %0, {%1, %2};" : "=l"(r) : "f"(a), "f"(b));
    return r;
}
__device__ __forceinline__ float2 unpack2(unsigned long long v) {
    float2 f;
    asm("mov.b64 {%0, %1}, %2;" : "=f"(f.x), "=f"(f.y) : "l"(v));
    return f;
}
__device__ __forceinline__ unsigned long long fma2(unsigned long long a,
                                                   unsigned long long b,
                                                   unsigned long long c) {
    unsigned long long d;
    asm("fma.rn.f32x2 %0, %1, %2, %3;" : "=l"(d) : "l"(a), "l"(b), "l"(c));
    return d;
}

// ---------------------------------------------------------------------------
// e2[k] = sum_d emb[k][d]^2, sequential d ascending (fp32, FMA)
// ---------------------------------------------------------------------------
__global__ void vq_e2_kernel(const float* __restrict__ emb) {
    int k = blockIdx.x * blockDim.x + threadIdx.x;
    if (k >= NK) return;
    const float* r = emb + k * ND;
    float s = 0.f;
#pragma unroll
    for (int d = 0; d < ND; d++) s = __fmaf_rn(r[d], r[d], s);
    g_e2[k] = s;
}

// ---------------------------------------------------------------------------
// Main kernel: 128 blocks x 128 threads, 2 points per thread.
//  - x for both points packed as (x_d, x_{d+1}) f32x2 pairs in registers
//  - codebook tile (8 codes x 64 dims = 2KB) staged to smem, ping-pong,
//    consumed as lane-uniform LDS.128 (broadcast) feeding 4 FFMA2 each
//  - dist = fl( fl(x2 - 2*dot) + e2 ), argmin with first-index tie-break
// ---------------------------------------------------------------------------
__global__ void __launch_bounds__(MAIN_THREADS) vq_main_kernel(
    const float* __restrict__ x_in,
    const float* __restrict__ emb,
    float* __restrict__ out)
{
    const int t    = threadIdx.x;
    const int base = blockIdx.x * 256;          // 256 points per block
    const int n0   = base + t;
    const int n1   = n0 + 128;
    const int b    = base >> 10;                // same batch for whole block (256 | 1024)
    const int hw0  = n0 & 1023;
    const int hw1  = hw0 + 128;

    const float* xp0p = x_in + (size_t)b * (ND * NHW) + hw0;
    const float* xp1p = x_in + (size_t)b * (ND * NHW) + hw1;

    // Load + pack x (coalesced across lanes); x2 accumulated in ascending d.
    unsigned long long xq0[32], xq1[32];
    float x2_0 = 0.f, x2_1 = 0.f;
#pragma unroll
    for (int p = 0; p < 32; p++) {
        float a0 = xp0p[(2 * p) * NHW], b0 = xp0p[(2 * p + 1) * NHW];
        float a1 = xp1p[(2 * p) * NHW], b1 = xp1p[(2 * p + 1) * NHW];
        x2_0 = __fmaf_rn(a0, a0, x2_0); x2_0 = __fmaf_rn(b0, b0, x2_0);
        x2_1 = __fmaf_rn(a1, a1, x2_1); x2_1 = __fmaf_rn(b1, b1, x2_1);
        xq0[p] = pack2(a0, b0);
        xq1[p] = pack2(a1, b1);
    }

    __shared__ float4 sbuf[2][CODES_PER_ITER * 16];   // 2 x 2KB ping-pong
    const float4* __restrict__ embf4 = (const float4*)emb;

    // Prologue stage: codes [0,8)
    sbuf[0][t] = embf4[t];
    __syncthreads();

    float best0 = CUDART_INF_F, best1 = CUDART_INF_F;
    int   bi0 = 0, bi1 = 0;

#pragma unroll 1
    for (int i = 0; i < NITER; i++) {
        const int cur = i & 1;
        if (i + 1 < NITER)
            sbuf[cur ^ 1][t] = embf4[(i + 1) * 128 + t];   // prefetch next tile

        const ulonglong2* __restrict__ sp = (const ulonglong2*)sbuf[cur];

        unsigned long long acc0[CODES_PER_ITER], acc1[CODES_PER_ITER];
#pragma unroll
        for (int j = 0; j < CODES_PER_ITER; j++) { acc0[j] = 0ull; acc1[j] = 0ull; }

#pragma unroll
        for (int j = 0; j < CODES_PER_ITER; j++) {
#pragma unroll
            for (int p2 = 0; p2 < 16; p2++) {
                ulonglong2 e = sp[j * 16 + p2];            // 16B broadcast LDS
                acc0[j] = fma2(xq0[2 * p2 + 0], e.x, acc0[j]);
                acc0[j] = fma2(xq0[2 * p2 + 1], e.y, acc0[j]);
                acc1[j] = fma2(xq1[2 * p2 + 0], e.x, acc1[j]);
                acc1[j] = fma2(xq1[2 * p2 + 1], e.y, acc1[j]);
            }
        }

        const int c0 = i * CODES_PER_ITER;
#pragma unroll
        for (int j = 0; j < CODES_PER_ITER; j++) {
            float e2v = g_e2[c0 + j];
            float2 a0 = unpack2(acc0[j]);
            float dot0 = __fadd_rn(a0.x, a0.y);
            float d0 = __fadd_rn(__fmaf_rn(-2.0f, dot0, x2_0), e2v);
            if (d0 < best0) { best0 = d0; bi0 = c0 + j; }
            float2 a1 = unpack2(acc1[j]);
            float dot1 = __fadd_rn(a1.x, a1.y);
            float d1 = __fadd_rn(__fmaf_rn(-2.0f, dot1, x2_1), e2v);
            if (d1 < best1) { best1 = d1; bi1 = c0 + j; }
        }
        __syncthreads();   // tile consumed; safe for prefetch of i+2 to land
    }

    // ---- epilogue: quantized output + loss partial --------------------------
    const float* er0  = emb + bi0 * ND;
    const float* er1  = emb + bi1 * ND;
    float* qout0 = out + 1 + (size_t)b * (ND * NHW) + hw0;
    float* qout1 = out + 1 + (size_t)b * (ND * NHW) + hw1;
    double lacc = 0.0;
#pragma unroll
    for (int p = 0; p < 32; p++) {
        float2 xv0 = unpack2(xq0[p]);
        float2 xv1 = unpack2(xq1[p]);
        float v00 = er0[2 * p], v01 = er0[2 * p + 1];
        float v10 = er1[2 * p], v11 = er1[2 * p + 1];
        qout0[(2 * p) * NHW]     = v00;
        qout0[(2 * p + 1) * NHW] = v01;
        qout1[(2 * p) * NHW]     = v10;
        qout1[(2 * p + 1) * NHW] = v11;
        float d00 = v00 - xv0.x, d01 = v01 - xv0.y;
        float d10 = v10 - xv1.x, d11 = v11 - xv1.y;
        lacc += (double)d00 * d00 + (double)d01 * d01;
        lacc += (double)d10 * d10 + (double)d11 * d11;
    }

    // indices (as float, exact below 2^24)
    out[1 + (size_t)NPTS * ND + n0] = (float)bi0;
    out[1 + (size_t)NPTS * ND + n1] = (float)bi1;

    // deterministic per-block double reduction of loss partial
    __shared__ double sd[MAIN_THREADS];
    sd[t] = lacc;
    __syncthreads();
#pragma unroll
    for (int s = MAIN_THREADS / 2; s > 0; s >>= 1) {
        if (t < s) sd[t] += sd[t + s];
        __syncthreads();
    }
    if (t == 0) g_partials[blockIdx.x] = sd[0];
}

// ---------------------------------------------------------------------------
// Final deterministic loss reduction: loss = 1.25 * mean((q - x)^2)
// (q_latent_loss + COMMITMENT_COST * e_latent_loss; the two terms are equal)
// ---------------------------------------------------------------------------
__global__ void vq_loss_kernel(float* __restrict__ out) {
    __shared__ double sd[MAIN_BLOCKS];
    int t = threadIdx.x;
    sd[t] = g_partials[t];
    __syncthreads();
#pragma unroll
    for (int s = MAIN_BLOCKS / 2; s > 0; s >>= 1) {
        if (t < s) sd[t] += sd[t + s];
        __syncthreads();
    }
    if (t == 0) out[0] = (float)(1.25 * sd[0] / (double)((size_t)NPTS * ND));
}

// ---------------------------------------------------------------------------
extern "C" void kernel_launch(void* const* d_in, const int* in_sizes, int n_in,
                              void* d_out, int out_size)
{
    const float* a = (const float*)d_in[0];   // inputs  [32,64,32,32]
    const float* e = (const float*)d_in[1];   // embedding [1024,64]
    // defensive: swap if metadata ordered the other way
    if (n_in >= 2 && in_sizes[0] == NK * ND && in_sizes[1] == NPTS * ND) {
        const float* t = a; a = e; e = t;
    }
    float* out = (float*)d_out;

    vq_e2_kernel  <<<(NK + 255) / 256, 256>>>(e);
    vq_main_kernel<<<MAIN_BLOCKS, MAIN_THREADS>>>(a, e, out);
    vq_loss_kernel<<<1, MAIN_BLOCKS>>>(out);
    (void)out_size;
}

// round 8
// speedup vs baseline: 1.4989x; 1.4989x over previous
#include <cuda_runtime.h>
#include <math_constants.h>

// VectorQuantizer: B=32, D=64, H=W=32, K=1024
// Output layout (f32 concat): [loss(1)][quantized BxDxHxW (2097152)][indices BxHW (32768)]

#define NB 32
#define ND 64
#define NHW 1024
#define NK 1024
#define NPTS 32768            // B*H*W
#define MAIN_BLOCKS 256       // 128 points per block, 1 point per thread
#define MAIN_THREADS 128
#define CODES_PER_ITER 16
#define NITER (NK / CODES_PER_ITER)   // 64

__device__ float  g_e2[NK];
__device__ double g_partials[MAIN_BLOCKS];

// ---------------------------------------------------------------------------
// Packed f32x2 helpers (Blackwell sm_103a; ptxas never auto-fuses these)
// ---------------------------------------------------------------------------
__device__ __forceinline__ unsigned long long pack2(float a, float b) {
    unsigned long long r;
    asm("mov.b64 %0, {%1, %2};" : "=l"(r) : "f"(a), "f"(b));
    return r;
}
__device__ __forceinline__ float2 unpack2(unsigned long long v) {
    float2 f;
    asm("mov.b64 {%0, %1}, %2;" : "=f"(f.x), "=f"(f.y) : "l"(v));
    return f;
}
__device__ __forceinline__ unsigned long long fma2(unsigned long long a,
                                                   unsigned long long b,
                                                   unsigned long long c) {
    unsigned long long d;
    asm("fma.rn.f32x2 %0, %1, %2, %3;" : "=l"(d) : "l"(a), "l"(b), "l"(c));
    return d;
}

// ---------------------------------------------------------------------------
// e2[k] = sum_d emb[k][d]^2, sequential d ascending (fp32, FMA)
// ---------------------------------------------------------------------------
__global__ void vq_e2_kernel(const float* __restrict__ emb) {
    int k = blockIdx.x * blockDim.x + threadIdx.x;
    if (k >= NK) return;
    const float* r = emb + k * ND;
    float s = 0.f;
#pragma unroll
    for (int d = 0; d < ND; d++) s = __fmaf_rn(r[d], r[d], s);
    g_e2[k] = s;
}

// ---------------------------------------------------------------------------
// Main kernel: 256 blocks x 128 threads, 1 point per thread (2 CTAs/SM).
//  - x packed as (x_d, x_{d+1}) f32x2 pairs in 32 regs
//  - codebook tile (16 codes x 64 dims = 4KB) staged to smem, ping-pong,
//    consumed as lane-uniform LDS.128 (broadcast), 16 independent FFMA2 chains
//  - dist = fl( fl(x2 - 2*dot) + e2 ), argmin with first-index tie-break
//  Numerics are bit-identical to the R5 passing kernel.
// ---------------------------------------------------------------------------
__global__ void __launch_bounds__(MAIN_THREADS, 2) vq_main_kernel(
    const float* __restrict__ x_in,
    const float* __restrict__ emb,
    float* __restrict__ out)
{
    const int t  = threadIdx.x;
    const int n  = blockIdx.x * MAIN_THREADS + t;   // point id (1 per thread)
    const int b  = n >> 10;
    const int hw = n & 1023;

    const float* xp = x_in + (size_t)b * (ND * NHW) + hw;

    // Load + pack x (coalesced across lanes); x2 accumulated in ascending d.
    unsigned long long xq[32];
    float x2 = 0.f;
#pragma unroll
    for (int p = 0; p < 32; p++) {
        float a = xp[(2 * p) * NHW];
        float c = xp[(2 * p + 1) * NHW];
        x2 = __fmaf_rn(a, a, x2);
        x2 = __fmaf_rn(c, c, x2);
        xq[p] = pack2(a, c);
    }

    // 16 codes * 64 floats = 256 float4 = 4KB per tile, x2 ping-pong
    __shared__ float4 sbuf[2][CODES_PER_ITER * 16];
    const float4* __restrict__ embf4 = (const float4*)emb;

    // Prologue stage: codes [0,16)
    sbuf[0][t]       = embf4[t];
    sbuf[0][t + 128] = embf4[t + 128];
    __syncthreads();

    float bestv = CUDART_INF_F;
    int   besti = 0;

#pragma unroll 1
    for (int i = 0; i < NITER; i++) {
        const int cur = i & 1;
        if (i + 1 < NITER) {
            sbuf[cur ^ 1][t]       = embf4[(i + 1) * 256 + t];
            sbuf[cur ^ 1][t + 128] = embf4[(i + 1) * 256 + 128 + t];
        }

        const ulonglong2* __restrict__ sp = (const ulonglong2*)sbuf[cur];

        unsigned long long acc[CODES_PER_ITER];
#pragma unroll
        for (int j = 0; j < CODES_PER_ITER; j++) acc[j] = 0ull;

#pragma unroll
        for (int j = 0; j < CODES_PER_ITER; j++) {
#pragma unroll
            for (int p2 = 0; p2 < 16; p2++) {
                ulonglong2 e = sp[j * 16 + p2];            // 16B broadcast LDS
                acc[j] = fma2(xq[2 * p2 + 0], e.x, acc[j]);
                acc[j] = fma2(xq[2 * p2 + 1], e.y, acc[j]);
            }
        }

        const int c0 = i * CODES_PER_ITER;
#pragma unroll
        for (int j = 0; j < CODES_PER_ITER; j++) {
            float e2v = g_e2[c0 + j];
            float2 a  = unpack2(acc[j]);
            float dot = __fadd_rn(a.x, a.y);
            float dv  = __fadd_rn(__fmaf_rn(-2.0f, dot, x2), e2v);
            if (dv < bestv) { bestv = dv; besti = c0 + j; }   // first-index ties
        }
        __syncthreads();   // tile consumed; safe for staging of i+2 to land
    }

    // ---- epilogue: quantized output + loss partial --------------------------
    const float* er   = emb + besti * ND;
    float*       qout = out + 1 + (size_t)b * (ND * NHW) + hw;
    double lacc = 0.0;
#pragma unroll
    for (int p = 0; p < 32; p++) {
        float2 xv = unpack2(xq[p]);
        float v0 = er[2 * p];
        float v1 = er[2 * p + 1];
        qout[(2 * p) * NHW]     = v0;   // coalesced across lanes
        qout[(2 * p + 1) * NHW] = v1;
        float d0 = v0 - xv.x;
        float d1 = v1 - xv.y;
        lacc += (double)d0 * d0 + (double)d1 * d1;
    }

    // indices (as float, exact below 2^24)
    out[1 + (size_t)NPTS * ND + n] = (float)besti;

    // deterministic per-block double reduction of loss partial
    __shared__ double sd[MAIN_THREADS];
    sd[t] = lacc;
    __syncthreads();
#pragma unroll
    for (int s = MAIN_THREADS / 2; s > 0; s >>= 1) {
        if (t < s) sd[t] += sd[t + s];
        __syncthreads();
    }
    if (t == 0) g_partials[blockIdx.x] = sd[0];
}

// ---------------------------------------------------------------------------
// Final deterministic loss reduction: loss = 1.25 * mean((q - x)^2)
// (q_latent_loss + COMMITMENT_COST * e_latent_loss; the two terms are equal)
// ---------------------------------------------------------------------------
__global__ void vq_loss_kernel(float* __restrict__ out) {
    __shared__ double sd[MAIN_BLOCKS];
    int t = threadIdx.x;
    sd[t] = g_partials[t];
    __syncthreads();
#pragma unroll
    for (int s = MAIN_BLOCKS / 2; s > 0; s >>= 1) {
        if (t < s) sd[t] += sd[t + s];
        __syncthreads();
    }
    if (t == 0) out[0] = (float)(1.25 * sd[0] / (double)((size_t)NPTS * ND));
}

// ---------------------------------------------------------------------------
extern "C" void kernel_launch(void* const* d_in, const int* in_sizes, int n_in,
                              void* d_out, int out_size)
{
    const float* a = (const float*)d_in[0];   // inputs  [32,64,32,32]
    const float* e = (const float*)d_in[1];   // embedding [1024,64]
    // defensive: swap if metadata ordered the other way
    if (n_in >= 2 && in_sizes[0] == NK * ND && in_sizes[1] == NPTS * ND) {
        const float* t = a; a = e; e = t;
    }
    float* out = (float*)d_out;

    vq_e2_kernel  <<<(NK + 255) / 256, 256>>>(e);
    vq_main_kernel<<<MAIN_BLOCKS, MAIN_THREADS>>>(a, e, out);
    vq_loss_kernel<<<1, MAIN_BLOCKS>>>(out);
    (void)out_size;
}

// round 9
// speedup vs baseline: 1.5021x; 1.0021x over previous
#include <cuda_runtime.h>
#include <math_constants.h>

// VectorQuantizer: B=32, D=64, H=W=32, K=1024
// Output layout (f32 concat): [loss(1)][quantized BxDxHxW (2097152)][indices BxHW (32768)]

#define NB 32
#define ND 64
#define NHW 1024
#define NK 1024
#define NPTS 32768            // B*H*W
#define MAIN_BLOCKS 256       // 128 points per block, 1 point per thread
#define MAIN_THREADS 128
#define CODES_PER_ITER 16
#define NITER (NK / CODES_PER_ITER)   // 64

__device__ float  g_e2[NK];
__device__ double g_partials[MAIN_BLOCKS];

// ---------------------------------------------------------------------------
// Packed f32x2 helpers (Blackwell sm_103a; ptxas never auto-fuses these)
// ---------------------------------------------------------------------------
__device__ __forceinline__ unsigned long long pack2(float a, float b) {
    unsigned long long r;
    asm("mov.b64 %0, {%1, %2};" : "=l"(r) : "f"(a), "f"(b));
    return r;
}
__device__ __forceinline__ float2 unpack2(unsigned long long v) {
    float2 f;
    asm("mov.b64 {%0, %1}, %2;" : "=f"(f.x), "=f"(f.y) : "l"(v));
    return f;
}
__device__ __forceinline__ unsigned long long fma2(unsigned long long a,
                                                   unsigned long long b,
                                                   unsigned long long c) {
    unsigned long long d;
    asm("fma.rn.f32x2 %0, %1, %2, %3;" : "=l"(d) : "l"(a), "l"(b), "l"(c));
    return d;
}

// ---------------------------------------------------------------------------
// e2[k] = sum_d emb[k][d]^2, sequential d ascending (fp32, FMA)
// ---------------------------------------------------------------------------
__global__ void vq_e2_kernel(const float* __restrict__ emb) {
    int k = blockIdx.x * blockDim.x + threadIdx.x;
    if (k >= NK) return;
    const float* r = emb + k * ND;
    float s = 0.f;
#pragma unroll
    for (int d = 0; d < ND; d++) s = __fmaf_rn(r[d], r[d], s);
    g_e2[k] = s;
}

// ---------------------------------------------------------------------------
// Main kernel: 256 blocks x 128 threads, 1 point per thread (2 CTAs/SM).
//  - x packed as (x_d, x_{d+1}) f32x2 pairs in 32 regs
//  - codebook tile (16 codes x 64 dims = 4KB) staged to smem, ping-pong,
//    consumed as lane-uniform LDS.128 (broadcast), 16 independent FFMA2 chains
//  - dist = fl( fl(x2 - 2*dot) + e2 ), argmin with first-index tie-break
//  Numerics are bit-identical to the R5 passing kernel.
// ---------------------------------------------------------------------------
__global__ void __launch_bounds__(MAIN_THREADS, 2) vq_main_kernel(
    const float* __restrict__ x_in,
    const float* __restrict__ emb,
    float* __restrict__ out)
{
    const int t  = threadIdx.x;
    const int n  = blockIdx.x * MAIN_THREADS + t;   // point id (1 per thread)
    const int b  = n >> 10;
    const int hw = n & 1023;

    const float* xp = x_in + (size_t)b * (ND * NHW) + hw;

    // Load + pack x (coalesced across lanes); x2 accumulated in ascending d.
    unsigned long long xq[32];
    float x2 = 0.f;
#pragma unroll
    for (int p = 0; p < 32; p++) {
        float a = xp[(2 * p) * NHW];
        float c = xp[(2 * p + 1) * NHW];
        x2 = __fmaf_rn(a, a, x2);
        x2 = __fmaf_rn(c, c, x2);
        xq[p] = pack2(a, c);
    }

    // 16 codes * 64 floats = 256 float4 = 4KB per tile, x2 ping-pong
    __shared__ float4 sbuf[2][CODES_PER_ITER * 16];
    const float4* __restrict__ embf4 = (const float4*)emb;

    // Prologue stage: codes [0,16)
    sbuf[0][t]       = embf4[t];
    sbuf[0][t + 128] = embf4[t + 128];
    __syncthreads();

    float bestv = CUDART_INF_F;
    int   besti = 0;

#pragma unroll 1
    for (int i = 0; i < NITER; i++) {
        const int cur = i & 1;
        if (i + 1 < NITER) {
            sbuf[cur ^ 1][t]       = embf4[(i + 1) * 256 + t];
            sbuf[cur ^ 1][t + 128] = embf4[(i + 1) * 256 + 128 + t];
        }

        const ulonglong2* __restrict__ sp = (const ulonglong2*)sbuf[cur];

        unsigned long long acc[CODES_PER_ITER];
#pragma unroll
        for (int j = 0; j < CODES_PER_ITER; j++) acc[j] = 0ull;

#pragma unroll
        for (int j = 0; j < CODES_PER_ITER; j++) {
#pragma unroll
            for (int p2 = 0; p2 < 16; p2++) {
                ulonglong2 e = sp[j * 16 + p2];            // 16B broadcast LDS
                acc[j] = fma2(xq[2 * p2 + 0], e.x, acc[j]);
                acc[j] = fma2(xq[2 * p2 + 1], e.y, acc[j]);
            }
        }

        const int c0 = i * CODES_PER_ITER;
#pragma unroll
        for (int j = 0; j < CODES_PER_ITER; j++) {
            float e2v = g_e2[c0 + j];
            float2 a  = unpack2(acc[j]);
            float dot = __fadd_rn(a.x, a.y);
            float dv  = __fadd_rn(__fmaf_rn(-2.0f, dot, x2), e2v);
            if (dv < bestv) { bestv = dv; besti = c0 + j; }   // first-index ties
        }
        __syncthreads();   // tile consumed; safe for staging of i+2 to land
    }

    // ---- epilogue: quantized output + loss partial --------------------------
    const float* er   = emb + besti * ND;
    float*       qout = out + 1 + (size_t)b * (ND * NHW) + hw;
    double lacc = 0.0;
#pragma unroll
    for (int p = 0; p < 32; p++) {
        float2 xv = unpack2(xq[p]);
        float v0 = er[2 * p];
        float v1 = er[2 * p + 1];
        qout[(2 * p) * NHW]     = v0;   // coalesced across lanes
        qout[(2 * p + 1) * NHW] = v1;
        float d0 = v0 - xv.x;
        float d1 = v1 - xv.y;
        lacc += (double)d0 * d0 + (double)d1 * d1;
    }

    // indices (as float, exact below 2^24)
    out[1 + (size_t)NPTS * ND + n] = (float)besti;

    // deterministic per-block double reduction of loss partial
    __shared__ double sd[MAIN_THREADS];
    sd[t] = lacc;
    __syncthreads();
#pragma unroll
    for (int s = MAIN_THREADS / 2; s > 0; s >>= 1) {
        if (t < s) sd[t] += sd[t + s];
        __syncthreads();
    }
    if (t == 0) g_partials[blockIdx.x] = sd[0];
}

// ---------------------------------------------------------------------------
// Final deterministic loss reduction: loss = 1.25 * mean((q - x)^2)
// (q_latent_loss + COMMITMENT_COST * e_latent_loss; the two terms are equal)
// ---------------------------------------------------------------------------
__global__ void vq_loss_kernel(float* __restrict__ out) {
    __shared__ double sd[MAIN_BLOCKS];
    int t = threadIdx.x;
    sd[t] = g_partials[t];
    __syncthreads();
#pragma unroll
    for (int s = MAIN_BLOCKS / 2; s > 0; s >>= 1) {
        if (t < s) sd[t] += sd[t + s];
        __syncthreads();
    }
    if (t == 0) out[0] = (float)(1.25 * sd[0] / (double)((size_t)NPTS * ND));
}

// ---------------------------------------------------------------------------
extern "C" void kernel_launch(void* const* d_in, const int* in_sizes, int n_in,
                              void* d_out, int out_size)
{
    const float* a = (const float*)d_in[0];   // inputs  [32,64,32,32]
    const float* e = (const float*)d_in[1];   // embedding [1024,64]
    // defensive: swap if metadata ordered the other way
    if (n_in >= 2 && in_sizes[0] == NK * ND && in_sizes[1] == NPTS * ND) {
        const float* t = a; a = e; e = t;
    }
    float* out = (float*)d_out;

    vq_e2_kernel  <<<(NK + 255) / 256, 256>>>(e);
    vq_main_kernel<<<MAIN_BLOCKS, MAIN_THREADS>>>(a, e, out);
    vq_loss_kernel<<<1, MAIN_BLOCKS>>>(out);
    (void)out_size;
}

// round 10
// speedup vs baseline: 1.7398x; 1.1582x over previous
#include <cuda_runtime.h>
#include <math_constants.h>

// VectorQuantizer: B=32, D=64, H=W=32, K=1024
// Output layout (f32 concat): [loss(1)][quantized BxDxHxW (2097152)][indices BxHW (32768)]

#define NB 32
#define ND 64
#define NHW 1024
#define NK 1024
#define NPTS 32768                 // B*H*W
#define CHUNK 4                    // codebook split per point
#define CODES_PER_CHUNK (NK / CHUNK)      // 256
#define CODES_PER_ITER 16
#define NITER (CODES_PER_CHUNK / CODES_PER_ITER)  // 16
#define SCAN_THREADS 128
#define SCAN_BLOCKS (CHUNK * NPTS / SCAN_THREADS) // 1024
#define COMB_THREADS 256
#define COMB_BLOCKS (NPTS / COMB_THREADS)         // 128

__device__ float              g_e2[NK];
__device__ unsigned long long g_part[CHUNK * NPTS];   // (dist_bits<<32)|code_idx
__device__ double             g_partials[COMB_BLOCKS];

// ---------------------------------------------------------------------------
// Packed f32x2 helpers (sm_103a FFMA2; ptxas never auto-fuses these)
// ---------------------------------------------------------------------------
__device__ __forceinline__ unsigned long long pack2(float a, float b) {
    unsigned long long r;
    asm("mov.b64 %0, {%1, %2};" : "=l"(r) : "f"(a), "f"(b));
    return r;
}
__device__ __forceinline__ float2 unpack2(unsigned long long v) {
    float2 f;
    asm("mov.b64 {%0, %1}, %2;" : "=f"(f.x), "=f"(f.y) : "l"(v));
    return f;
}
__device__ __forceinline__ unsigned long long fma2(unsigned long long a,
                                                   unsigned long long b,
                                                   unsigned long long c) {
    unsigned long long d;
    asm("fma.rn.f32x2 %0, %1, %2, %3;" : "=l"(d) : "l"(a), "l"(b), "l"(c));
    return d;
}

// ---------------------------------------------------------------------------
// e2[k] = sum_d emb[k][d]^2 — 8 lanes per code, shfl reduce (latency-optimized;
// reduction-order change perturbs dist by ~1e-12, far below the fp32 ULP grid)
// ---------------------------------------------------------------------------
__global__ void vq_e2_kernel(const float* __restrict__ emb) {
    int tid = blockIdx.x * 256 + threadIdx.x;   // 8192 threads
    int k   = tid >> 3;
    int sub = tid & 7;
    const float* r = emb + k * ND + sub * 8;
    float s = 0.f;
#pragma unroll
    for (int d = 0; d < 8; d++) s = __fmaf_rn(r[d], r[d], s);
    s += __shfl_down_sync(0xffffffffu, s, 4, 8);
    s += __shfl_down_sync(0xffffffffu, s, 2, 8);
    s += __shfl_down_sync(0xffffffffu, s, 1, 8);
    if (sub == 0) g_e2[k] = s;
}

// ---------------------------------------------------------------------------
// Scan kernel: 4096... actually 1024 CTAs x 128 threads.
//   blockIdx = point-group (256) x chunk (4). Each thread: 1 point, 256 codes.
//   Per-code dot order is bit-identical to the R5/R9 passing kernels.
//   Result packed (dist_bits<<32)|global_code_idx -> u64 min == reference's
//   strict-< ascending-index argmin (dist > 0 so float bits are monotone).
// ---------------------------------------------------------------------------
__global__ void __launch_bounds__(SCAN_THREADS, 4) vq_scan_kernel(
    const float* __restrict__ x_in,
    const float* __restrict__ emb,
    float* __restrict__ /*unused*/ out)
{
    const int t  = threadIdx.x;
    const int c  = blockIdx.x & (CHUNK - 1);      // chunk id 0..3
    const int g  = blockIdx.x >> 2;               // point group 0..255
    const int n  = g * SCAN_THREADS + t;          // point id
    const int b  = n >> 10;
    const int hw = n & 1023;

    const float* xp = x_in + (size_t)b * (ND * NHW) + hw;

    // Load + pack x (coalesced across lanes); x2 in ascending d (as before).
    unsigned long long xq[32];
    float x2 = 0.f;
#pragma unroll
    for (int p = 0; p < 32; p++) {
        float a  = xp[(2 * p) * NHW];
        float cc = xp[(2 * p + 1) * NHW];
        x2 = __fmaf_rn(a, a, x2);
        x2 = __fmaf_rn(cc, cc, x2);
        xq[p] = pack2(a, cc);
    }

    // Tiles: 16 codes * 64 floats = 256 float4 = 4KB, ping-pong
    __shared__ float4 sbuf[2][CODES_PER_ITER * 16];
    const float4* __restrict__ embc =
        (const float4*)emb + (size_t)c * CODES_PER_CHUNK * 16;

    sbuf[0][t]       = embc[t];
    sbuf[0][t + 128] = embc[t + 128];
    __syncthreads();

    float bestv = CUDART_INF_F;
    int   besti = 0;
    const int code_base = c * CODES_PER_CHUNK;

#pragma unroll 1
    for (int i = 0; i < NITER; i++) {
        const int cur = i & 1;
        if (i + 1 < NITER) {
            sbuf[cur ^ 1][t]       = embc[(i + 1) * 256 + t];
            sbuf[cur ^ 1][t + 128] = embc[(i + 1) * 256 + 128 + t];
        }

        const ulonglong2* __restrict__ sp = (const ulonglong2*)sbuf[cur];

        unsigned long long acc[CODES_PER_ITER];
#pragma unroll
        for (int j = 0; j < CODES_PER_ITER; j++) acc[j] = 0ull;

#pragma unroll
        for (int j = 0; j < CODES_PER_ITER; j++) {
#pragma unroll
            for (int p2 = 0; p2 < 16; p2++) {
                ulonglong2 e = sp[j * 16 + p2];            // 16B broadcast LDS
                acc[j] = fma2(xq[2 * p2 + 0], e.x, acc[j]);
                acc[j] = fma2(xq[2 * p2 + 1], e.y, acc[j]);
            }
        }

        const int c0 = code_base + i * CODES_PER_ITER;
#pragma unroll
        for (int j = 0; j < CODES_PER_ITER; j++) {
            float e2v = g_e2[c0 + j];
            float2 a  = unpack2(acc[j]);
            float dot = __fadd_rn(a.x, a.y);
            float dv  = __fadd_rn(__fmaf_rn(-2.0f, dot, x2), e2v);
            if (dv < bestv) { bestv = dv; besti = c0 + j; }   // first-index ties
        }
        __syncthreads();
    }

    // dist >= 0 here (||x-e||^2, x2~64), so float bits are order-preserving.
    unsigned long long packed =
        ((unsigned long long)__float_as_uint(bestv) << 32) | (unsigned)besti;
    g_part[(size_t)c * NPTS + n] = packed;
    (void)out;
}

// ---------------------------------------------------------------------------
// Combine: u64-min over 4 chunk partials, then gather/quantized/index/loss.
// ---------------------------------------------------------------------------
__global__ void __launch_bounds__(COMB_THREADS) vq_combine_kernel(
    const float* __restrict__ x_in,
    const float* __restrict__ emb,
    float* __restrict__ out)
{
    const int t  = threadIdx.x;
    const int n  = blockIdx.x * COMB_THREADS + t;
    const int b  = n >> 10;
    const int hw = n & 1023;

    unsigned long long m = g_part[n];
#pragma unroll
    for (int c = 1; c < CHUNK; c++) {
        unsigned long long v = g_part[(size_t)c * NPTS + n];
        if (v < m) m = v;        // lower dist wins; equal dist -> lower index
    }
    const int besti = (int)(m & 0xffffffffu);

    const float* xp   = x_in + (size_t)b * (ND * NHW) + hw;
    const float* er   = emb + (size_t)besti * ND;
    float*       qout = out + 1 + (size_t)b * (ND * NHW) + hw;

    double lacc = 0.0;
#pragma unroll
    for (int d = 0; d < ND; d++) {
        float v = er[d];                 // gather (embedding L2-hot)
        qout[d * NHW] = v;               // coalesced across lanes
        float diff = v - xp[d * NHW];
        lacc += (double)diff * (double)diff;
    }

    out[1 + (size_t)NPTS * ND + n] = (float)besti;   // exact below 2^24

    __shared__ double sd[COMB_THREADS];
    sd[t] = lacc;
    __syncthreads();
#pragma unroll
    for (int s = COMB_THREADS / 2; s > 0; s >>= 1) {
        if (t < s) sd[t] += sd[t + s];
        __syncthreads();
    }
    if (t == 0) g_partials[blockIdx.x] = sd[0];
}

// ---------------------------------------------------------------------------
// Final deterministic loss reduction: loss = 1.25 * mean((q - x)^2)
// ---------------------------------------------------------------------------
__global__ void vq_loss_kernel(float* __restrict__ out) {
    __shared__ double sd[COMB_BLOCKS];
    int t = threadIdx.x;
    sd[t] = g_partials[t];
    __syncthreads();
#pragma unroll
    for (int s = COMB_BLOCKS / 2; s > 0; s >>= 1) {
        if (t < s) sd[t] += sd[t + s];
        __syncthreads();
    }
    if (t == 0) out[0] = (float)(1.25 * sd[0] / (double)((size_t)NPTS * ND));
}

// ---------------------------------------------------------------------------
extern "C" void kernel_launch(void* const* d_in, const int* in_sizes, int n_in,
                              void* d_out, int out_size)
{
    const float* a = (const float*)d_in[0];   // inputs  [32,64,32,32]
    const float* e = (const float*)d_in[1];   // embedding [1024,64]
    if (n_in >= 2 && in_sizes[0] == NK * ND && in_sizes[1] == NPTS * ND) {
        const float* t = a; a = e; e = t;     // defensive order swap
    }
    float* out = (float*)d_out;

    vq_e2_kernel     <<<32, 256>>>(e);                       // 8192 threads
    vq_scan_kernel   <<<SCAN_BLOCKS, SCAN_THREADS>>>(a, e, out);
    vq_combine_kernel<<<COMB_BLOCKS, COMB_THREADS>>>(a, e, out);
    vq_loss_kernel   <<<1, COMB_BLOCKS>>>(out);
    (void)out_size;
}